// round 9
// baseline (speedup 1.0000x reference)
#include <cuda_runtime.h>
#include <cuda_fp16.h>
#include <cstdint>

// out[n,o] = sum_i x[n,i] * sign(W[o,i]) + b[o],  N=IN=OUT=4096, fp32 in/out.
//
// Legacy HMMA f32-acc mma.sync (tcgen05 not emittable at compute_103).
// Round-7 evidence: smem crossbar (96 B/cyc of 128) co-binds with tensor; occ
// doesn't help. Round-8/9: B = sign(W) carried as PACKED BITS (1 KB/ktile in
// smem instead of 16 KB fp16); B fragments synthesized in registers.
// Round-9 fix: hi-half fp16 sign bit is bit 31 (was wrongly flipping bit 30,
// producing -inf). CTA 128x128, 4 warps 64x64, K-tile 64, 3-stage, 2 CTAs/SM.

#define N_DIM 4096
constexpr int MTILE = 128;
constexpr int NTILE = 128;
constexpr int KTILE = 64;
constexpr int NKT = N_DIM / KTILE;               // 64
constexpr int BITS_OFF = 16384;                  // A tile is 16KB
constexpr int STAGE_BYTES = 16384 + 1024;        // A + bit tile
constexpr int SMEM_BYTES = 3 * STAGE_BYTES;      // 52224

__device__ __half   g_xh[(size_t)N_DIM * N_DIM];
// chunk-major bit matrix: g_wbits[c * 4096 + n] = 64 k-bits (k = c*64 + j),
// bit j = 1 iff W[n][c*64+j] > 0  (else weight -1)
__device__ uint64_t g_wbits[(size_t)(N_DIM / 64) * N_DIM];

// ---------------------------------------------------------------------------
// prep: cast x -> fp16
// ---------------------------------------------------------------------------
__global__ void prep_x(const float4* __restrict__ x, int n4) {
    int i = blockIdx.x * blockDim.x + threadIdx.x;
    if (i >= n4) return;
    float4 xv = x[i];
    alignas(8) __half xh[4];
    xh[0] = __float2half_rn(xv.x);
    xh[1] = __float2half_rn(xv.y);
    xh[2] = __float2half_rn(xv.z);
    xh[3] = __float2half_rn(xv.w);
    *reinterpret_cast<uint2*>(g_xh + (size_t)i * 4) = *reinterpret_cast<uint2*>(xh);
}

// prep: pack sign(W) into bits, one warp per W row, ballot over 32 lanes
__global__ void prep_w(const float* __restrict__ W) {
    int gwarp = (blockIdx.x * blockDim.x + threadIdx.x) >> 5;   // row n
    int lane  = threadIdx.x & 31;
    if (gwarp >= N_DIM) return;
    const float* row = W + (size_t)gwarp * N_DIM;
#pragma unroll 4
    for (int c = 0; c < 64; c++) {
        float v0 = row[c * 64 + lane];
        float v1 = row[c * 64 + 32 + lane];
        uint32_t lo = __ballot_sync(0xFFFFFFFFu, v0 > 0.0f);
        uint32_t hi = __ballot_sync(0xFFFFFFFFu, v1 > 0.0f);
        if (lane == 0)
            g_wbits[(size_t)c * N_DIM + gwarp] = (uint64_t)lo | ((uint64_t)hi << 32);
    }
}

// ---------------------------------------------------------------------------
// PTX helpers
// ---------------------------------------------------------------------------
__device__ __forceinline__ void cp16(uint32_t smem_addr, const void* gmem_ptr) {
    asm volatile("cp.async.cg.shared.global [%0], [%1], 16;\n"
                 :: "r"(smem_addr), "l"(gmem_ptr) : "memory");
}

__device__ __forceinline__ void cp8(uint32_t smem_addr, const void* gmem_ptr) {
    asm volatile("cp.async.ca.shared.global [%0], [%1], 8;\n"
                 :: "r"(smem_addr), "l"(gmem_ptr) : "memory");
}

__device__ __forceinline__ void ldsm_x4(uint32_t* r, uint32_t a) {
    asm volatile("ldmatrix.sync.aligned.m8n8.x4.shared.b16 {%0,%1,%2,%3}, [%4];\n"
                 : "=r"(r[0]), "=r"(r[1]), "=r"(r[2]), "=r"(r[3]) : "r"(a));
}

__device__ __forceinline__ void mma16816(float* d, const uint32_t* a,
                                         const uint32_t* b) {
    asm volatile("mma.sync.aligned.m16n8k16.row.col.f32.f16.f16.f32 "
                 "{%0,%1,%2,%3},{%4,%5,%6,%7},{%8,%9},{%0,%1,%2,%3};\n"
                 : "+f"(d[0]), "+f"(d[1]), "+f"(d[2]), "+f"(d[3])
                 : "r"(a[0]), "r"(a[1]), "r"(a[2]), "r"(a[3]),
                   "r"(b[0]), "r"(b[1]));
}

// 2 sign bits (s bit0 -> fp16 lo, s bit1 -> fp16 hi) -> packed fp16x2 of +/-1
// lo fp16 sign = bit 15, hi fp16 sign = bit 31.
__device__ __forceinline__ uint32_t bexp(uint32_t s) {
    return 0xBC00BC00u ^ ((s << 15) & 0x8000u) ^ ((s << 30) & 0x80000000u);
}

// ---------------------------------------------------------------------------
// GEMM: 128 threads = 4 warps in 2(M) x 2(N), warp tile 64x64.
// Stage: A rows 0-127 (128B/row XOR-swizzled) at 0; 128 x uint64 bits at 16384.
// ---------------------------------------------------------------------------
__global__ void __launch_bounds__(128, 2)
gemm_kernel(const float* __restrict__ bias, float* __restrict__ out) {
    extern __shared__ char smem[];
    const uint32_t smem_base = (uint32_t)__cvta_generic_to_shared(smem);
    const int tid   = threadIdx.x;
    const int lane  = tid & 31;
    const int warp  = tid >> 5;
    const int warpM = warp & 1;
    const int warpN = warp >> 1;
    const int mBase = blockIdx.y * MTILE;
    const int nBase = blockIdx.x * NTILE;

    float acc[4][8][4];
#pragma unroll
    for (int a = 0; a < 4; a++)
#pragma unroll
        for (int b = 0; b < 8; b++)
#pragma unroll
            for (int c = 0; c < 4; c++) acc[a][b][c] = 0.0f;

    // ---- cp.async A mapping: ch16 = tid&7, rows rbase + p*16 ----
    const int rbase = tid >> 3;
    const int ch    = tid & 7;
    const uint32_t swA = (uint32_t)rbase * 128 + (uint32_t)((ch ^ (rbase & 7)) << 4);
    const __half* gA = g_xh + (size_t)(mBase + rbase) * N_DIM + ch * 8;

    auto prefetch = [&](int kt) {
        const uint32_t sb = smem_base + (uint32_t)(kt % 3) * STAGE_BYTES;
        const int k0 = kt * KTILE;
#pragma unroll
        for (int p = 0; p < 8; p++)
            cp16(sb + swA + (uint32_t)p * 2048, gA + (size_t)p * 16 * N_DIM + k0);
        // bits: one uint64 per thread, coalesced (chunk-major layout)
        cp8(sb + BITS_OFF + (uint32_t)tid * 8,
            g_wbits + (size_t)kt * N_DIM + nBase + tid);
        asm volatile("cp.async.commit_group;\n" ::: "memory");
    };

    // ---- ldmatrix A per-thread offsets ----
    const uint32_t la7 = lane & 7;
    const uint32_t aHi = (lane >> 4) & 1;
    uint32_t aOff[4];
#pragma unroll
    for (int tm = 0; tm < 4; tm++)
        aOff[tm] = (uint32_t)(warpM * 64 + tm * 16 + (lane & 15)) * 128;

    const int nLoc  = warpN * 64 + (lane >> 2);   // local n of this thread's B col
    const int pos0  = 2 * (lane & 3);

    auto compute = [&](int stg) {
        const uint32_t sb = smem_base + (uint32_t)stg * STAGE_BYTES;
        // load this thread's 8 bit-words (broadcast LDS.64, conflict-free)
        const uint64_t* bw =
            reinterpret_cast<const uint64_t*>(smem + (size_t)stg * STAGE_BYTES + BITS_OFF);
        uint64_t w[8];
#pragma unroll
        for (int pr = 0; pr < 4; pr++) {
            w[2 * pr]     = bw[nLoc + pr * 16];
            w[2 * pr + 1] = bw[nLoc + pr * 16 + 8];
        }
#pragma unroll
        for (int ks = 0; ks < 4; ks++) {
            const uint32_t ca = ((ks * 2 + aHi) ^ la7) << 4;
            uint32_t ah[4][4];
#pragma unroll
            for (int tm = 0; tm < 4; tm++) ldsm_x4(ah[tm], sb + aOff[tm] + ca);
            const int pos = ks * 16 + pos0;
#pragma unroll
            for (int pr = 0; pr < 4; pr++) {
                uint32_t sa = (uint32_t)(w[2 * pr] >> pos);
                uint32_t sc = (uint32_t)(w[2 * pr + 1] >> pos);
                uint32_t bq[4];
                bq[0] = bexp(sa);
                bq[1] = bexp(sa >> 8);
                bq[2] = bexp(sc);
                bq[3] = bexp(sc >> 8);
#pragma unroll
                for (int tm = 0; tm < 4; tm++) {
                    mma16816(acc[tm][2 * pr],     ah[tm], &bq[0]);
                    mma16816(acc[tm][2 * pr + 1], ah[tm], &bq[2]);
                }
            }
        }
    };

    prefetch(0);
    prefetch(1);

    for (int kt = 0; kt < NKT; kt++) {
        if (kt + 1 < NKT)
            asm volatile("cp.async.wait_group 1;\n" ::: "memory");
        else
            asm volatile("cp.async.wait_group 0;\n" ::: "memory");
        __syncthreads();
        if (kt + 2 < NKT) prefetch(kt + 2);
        compute(kt % 3);
    }

    // ---- epilogue: + bias, fp32 store ----
    const int g  = lane >> 2;
    const int t4 = lane & 3;
#pragma unroll
    for (int tm = 0; tm < 4; tm++) {
        int rr = mBase + warpM * 64 + tm * 16 + g;
#pragma unroll
        for (int tn = 0; tn < 8; tn++) {
            int col = nBase + warpN * 64 + tn * 8 + 2 * t4;
            float2 b2 = *reinterpret_cast<const float2*>(bias + col);
            float2 v0, v1;
            v0.x = acc[tm][tn][0] + b2.x;
            v0.y = acc[tm][tn][1] + b2.y;
            v1.x = acc[tm][tn][2] + b2.x;
            v1.y = acc[tm][tn][3] + b2.y;
            *reinterpret_cast<float2*>(out + (size_t)rr * N_DIM + col)       = v0;
            *reinterpret_cast<float2*>(out + (size_t)(rr + 8) * N_DIM + col) = v1;
        }
    }
}

// ---------------------------------------------------------------------------
extern "C" void kernel_launch(void* const* d_in, const int* in_sizes, int n_in,
                              void* d_out, int out_size) {
    const float* x = (const float*)d_in[0];
    const float* W = (const float*)d_in[1];
    const float* b = (const float*)d_in[2];
    float* out = (float*)d_out;

    const int n4 = (N_DIM * N_DIM) / 4;
    prep_x<<<(n4 + 255) / 256, 256>>>((const float4*)x, n4);
    prep_w<<<(N_DIM * 32 + 255) / 256, 256>>>(W);

    cudaFuncSetAttribute(gemm_kernel, cudaFuncAttributeMaxDynamicSharedMemorySize,
                         SMEM_BYTES);
    dim3 grid(N_DIM / NTILE, N_DIM / MTILE);  // (32, 32)
    gemm_kernel<<<grid, 128, SMEM_BYTES>>>(b, out);
}

// round 10
// speedup vs baseline: 1.1744x; 1.1744x over previous
#include <cuda_runtime.h>
#include <cuda_fp16.h>
#include <cstdint>

// out[n,o] = sum_i x[n,i] * sign(W[o,i]) + b[o],  N=IN=OUT=4096, fp32 in/out.
//
// Legacy HMMA f32-acc mma.sync (tcgen05 not emittable at compute_103).
// Round-9 evidence: smem bandwidth is NOT the binding factor (bit-packed B cut
// traffic 40% and regressed); the ~74% tensor ceiling is LDSM->MMA dependency
// heads at each ks step. Round-10: fp16 A+B in smem (round-6 shape) plus
// REGISTER FRAGMENT DOUBLE-BUFFERING: ldmatrix for ks+1 issues while ks's 32
// MMAs occupy the tensor pipe. CTA 128x128, 4 warps 64x64, K-tile 64, 3-stage
// cp.async, XOR swizzle, 2 CTAs/SM.

#define N_DIM 4096
constexpr int MTILE = 128;
constexpr int NTILE = 128;
constexpr int KTILE = 64;
constexpr int NKT = N_DIM / KTILE;           // 64
constexpr int STAGE_BYTES = 2 * 128 * 128;   // A 16KB + B 16KB
constexpr int SMEM_BYTES = 3 * STAGE_BYTES;  // 98304

__device__ __half g_xh[(size_t)N_DIM * N_DIM];
__device__ __half g_wb[(size_t)N_DIM * N_DIM];

// ---------------------------------------------------------------------------
// prep: binarize W -> fp16, cast x -> fp16
// ---------------------------------------------------------------------------
__global__ void prep_kernel(const float4* __restrict__ x,
                            const float4* __restrict__ W, int n4) {
    int i = blockIdx.x * blockDim.x + threadIdx.x;
    if (i >= n4) return;
    float4 xv = x[i];
    float4 wv = W[i];
    float xs[4] = {xv.x, xv.y, xv.z, xv.w};
    float ws[4] = {wv.x, wv.y, wv.z, wv.w};
    alignas(8) __half xh[4], wb[4];
#pragma unroll
    for (int j = 0; j < 4; j++) {
        xh[j] = __float2half_rn(xs[j]);
        float s = (ws[j] > 0.0f) ? 1.0f : ((ws[j] < 0.0f) ? -1.0f : 0.0f);
        wb[j] = __float2half_rn(s);
    }
    size_t base = (size_t)i * 4;
    *reinterpret_cast<uint2*>(g_xh + base) = *reinterpret_cast<uint2*>(xh);
    *reinterpret_cast<uint2*>(g_wb + base) = *reinterpret_cast<uint2*>(wb);
}

// ---------------------------------------------------------------------------
// PTX helpers
// ---------------------------------------------------------------------------
__device__ __forceinline__ void cp16(uint32_t smem_addr, const void* gmem_ptr) {
    asm volatile("cp.async.cg.shared.global [%0], [%1], 16;\n"
                 :: "r"(smem_addr), "l"(gmem_ptr) : "memory");
}

__device__ __forceinline__ void ldsm_x4(uint32_t* r, uint32_t a) {
    asm volatile("ldmatrix.sync.aligned.m8n8.x4.shared.b16 {%0,%1,%2,%3}, [%4];\n"
                 : "=r"(r[0]), "=r"(r[1]), "=r"(r[2]), "=r"(r[3]) : "r"(a));
}

__device__ __forceinline__ void mma16816(float* d, const uint32_t* a,
                                         const uint32_t* b) {
    asm volatile("mma.sync.aligned.m16n8k16.row.col.f32.f16.f16.f32 "
                 "{%0,%1,%2,%3},{%4,%5,%6,%7},{%8,%9},{%0,%1,%2,%3};\n"
                 : "+f"(d[0]), "+f"(d[1]), "+f"(d[2]), "+f"(d[3])
                 : "r"(a[0]), "r"(a[1]), "r"(a[2]), "r"(a[3]),
                   "r"(b[0]), "r"(b[1]));
}

// ---------------------------------------------------------------------------
// GEMM: 128 threads = 4 warps in 2(M) x 2(N), warp tile 64x64.
// Stage layout: A rows 0-127 (128B/row XOR-swizzled); B at +16384 same.
// Swizzle: byte_off(row, ch16) = row*128 + ((ch16 ^ (row&7)) << 4)
// ---------------------------------------------------------------------------
__global__ void __launch_bounds__(128, 2)
gemm_kernel(const float* __restrict__ bias, float* __restrict__ out) {
    extern __shared__ char smem[];
    const uint32_t smem_base = (uint32_t)__cvta_generic_to_shared(smem);
    const int tid   = threadIdx.x;
    const int lane  = tid & 31;
    const int warp  = tid >> 5;
    const int warpM = warp & 1;
    const int warpN = warp >> 1;
    const int mBase = blockIdx.y * MTILE;
    const int nBase = blockIdx.x * NTILE;

    float acc[4][8][4];
#pragma unroll
    for (int a = 0; a < 4; a++)
#pragma unroll
        for (int b = 0; b < 8; b++)
#pragma unroll
            for (int c = 0; c < 4; c++) acc[a][b][c] = 0.0f;

    // ---- cp.async per-thread mapping: ch16 = tid&7, rows rbase + p*16 ----
    const int rbase = tid >> 3;               // 0..15
    const int ch    = tid & 7;
    const uint32_t swA = (uint32_t)rbase * 128 + (uint32_t)((ch ^ (rbase & 7)) << 4);
    const __half* gA = g_xh + (size_t)(mBase + rbase) * N_DIM + ch * 8;
    const __half* gB = g_wb + (size_t)(nBase + rbase) * N_DIM + ch * 8;

    auto prefetch = [&](int kt) {
        const uint32_t sb = smem_base + (uint32_t)(kt % 3) * STAGE_BYTES;
        const int k0 = kt * KTILE;
#pragma unroll
        for (int p = 0; p < 8; p++) {
            uint32_t so = swA + (uint32_t)p * 2048;      // +16 rows
            size_t go = (size_t)p * 16 * N_DIM + k0;
            cp16(sb + so,         gA + go);
            cp16(sb + 16384 + so, gB + go);
        }
        asm volatile("cp.async.commit_group;\n" ::: "memory");
    };

    // ---- ldmatrix per-thread row/offset precompute ----
    const uint32_t la7 = lane & 7;
    const uint32_t aHi = (lane >> 4) & 1;     // k +8 selector for A
    const uint32_t bHi = (lane >> 3) & 1;     // k +8 selector for B
    uint32_t aOff[4], bOff[4];
#pragma unroll
    for (int tm = 0; tm < 4; tm++) {
        uint32_t r = warpM * 64 + tm * 16 + (lane & 15);
        aOff[tm] = r * 128;
    }
#pragma unroll
    for (int pr = 0; pr < 4; pr++) {
        uint32_t r = warpN * 64 + pr * 16 + la7 + ((lane >> 4) & 1) * 8;
        bOff[pr] = 16384 + r * 128;
    }

    uint32_t ah[2][4][4], bq[2][4][4];

    auto loadfrags = [&](uint32_t sb, int ks, int buf) {
        const uint32_t ca = (((uint32_t)ks * 2 + aHi) ^ la7) << 4;
        const uint32_t cb = (((uint32_t)ks * 2 + bHi) ^ la7) << 4;
#pragma unroll
        for (int tm = 0; tm < 4; tm++) ldsm_x4(ah[buf][tm], sb + aOff[tm] + ca);
#pragma unroll
        for (int pr = 0; pr < 4; pr++) ldsm_x4(bq[buf][pr], sb + bOff[pr] + cb);
    };

    auto mmas = [&](int buf) {
#pragma unroll
        for (int tm = 0; tm < 4; tm++)
#pragma unroll
            for (int pr = 0; pr < 4; pr++) {
                mma16816(acc[tm][2 * pr],     ah[buf][tm], &bq[buf][pr][0]);
                mma16816(acc[tm][2 * pr + 1], ah[buf][tm], &bq[buf][pr][2]);
            }
    };

    prefetch(0);
    prefetch(1);

    for (int kt = 0; kt < NKT; kt++) {
        if (kt + 1 < NKT)
            asm volatile("cp.async.wait_group 1;\n" ::: "memory");
        else
            asm volatile("cp.async.wait_group 0;\n" ::: "memory");
        __syncthreads();
        if (kt + 2 < NKT) prefetch(kt + 2);
        const uint32_t sb = smem_base + (uint32_t)(kt % 3) * STAGE_BYTES;
        // fragment-pipelined k-tile: load ks+1 while ks's MMAs run
        loadfrags(sb, 0, 0);
#pragma unroll
        for (int ks = 0; ks < 4; ks++) {
            const int cur = ks & 1;
            if (ks < 3) loadfrags(sb, ks + 1, cur ^ 1);
            mmas(cur);
        }
    }

    // ---- epilogue: + bias, fp32 store ----
    const int g  = lane >> 2;
    const int t4 = lane & 3;
#pragma unroll
    for (int tm = 0; tm < 4; tm++) {
        int rr = mBase + warpM * 64 + tm * 16 + g;
#pragma unroll
        for (int tn = 0; tn < 8; tn++) {
            int col = nBase + warpN * 64 + tn * 8 + 2 * t4;
            float2 b2 = *reinterpret_cast<const float2*>(bias + col);
            float2 v0, v1;
            v0.x = acc[tm][tn][0] + b2.x;
            v0.y = acc[tm][tn][1] + b2.y;
            v1.x = acc[tm][tn][2] + b2.x;
            v1.y = acc[tm][tn][3] + b2.y;
            *reinterpret_cast<float2*>(out + (size_t)rr * N_DIM + col)       = v0;
            *reinterpret_cast<float2*>(out + (size_t)(rr + 8) * N_DIM + col) = v1;
        }
    }
}

// ---------------------------------------------------------------------------
extern "C" void kernel_launch(void* const* d_in, const int* in_sizes, int n_in,
                              void* d_out, int out_size) {
    const float* x = (const float*)d_in[0];
    const float* W = (const float*)d_in[1];
    const float* b = (const float*)d_in[2];
    float* out = (float*)d_out;

    const int n4 = (N_DIM * N_DIM) / 4;
    prep_kernel<<<(n4 + 255) / 256, 256>>>((const float4*)x, (const float4*)W, n4);

    cudaFuncSetAttribute(gemm_kernel, cudaFuncAttributeMaxDynamicSharedMemorySize,
                         SMEM_BYTES);
    dim3 grid(N_DIM / NTILE, N_DIM / MTILE);  // (32, 32)
    gemm_kernel<<<grid, 128, SMEM_BYTES>>>(b, out);
}

// round 11
// speedup vs baseline: 1.3017x; 1.1084x over previous
#include <cuda_runtime.h>
#include <cuda_fp16.h>
#include <cstdint>

// out[n,o] = sum_i x[n,i] * sign(W[o,i]) + b[o],  N=IN=OUT=4096, fp32 in/out.
//
// Legacy HMMA f32-acc mma.sync (tcgen05 not emittable at compute_103).
// Rounds 6-10 evidence: ~74% tensor ceiling = wave quantization (86.5%) x
// per-ktile sync head. Round-11: carry ks3's MMAs ACROSS the barrier — each
// warp reaches __syncthreads with one fragment set still un-crunched, issues
// next ktile's ks0 LDSM right after the barrier, then retires ks3, keeping the
// tensor pipe busy through the sync window. CTA 128x128, 4 warps 64x64,
// K-tile 64, 3-stage cp.async, XOR swizzle, 2 CTAs/SM.

#define N_DIM 4096
constexpr int MTILE = 128;
constexpr int NTILE = 128;
constexpr int KTILE = 64;
constexpr int NKT = N_DIM / KTILE;           // 64
constexpr int STAGE_BYTES = 2 * 128 * 128;   // A 16KB + B 16KB
constexpr int SMEM_BYTES = 3 * STAGE_BYTES;  // 98304

__device__ __half g_xh[(size_t)N_DIM * N_DIM];
__device__ __half g_wb[(size_t)N_DIM * N_DIM];

// ---------------------------------------------------------------------------
// prep: binarize W -> fp16, cast x -> fp16
// ---------------------------------------------------------------------------
__global__ void prep_kernel(const float4* __restrict__ x,
                            const float4* __restrict__ W, int n4) {
    int i = blockIdx.x * blockDim.x + threadIdx.x;
    if (i >= n4) return;
    float4 xv = x[i];
    float4 wv = W[i];
    float xs[4] = {xv.x, xv.y, xv.z, xv.w};
    float ws[4] = {wv.x, wv.y, wv.z, wv.w};
    alignas(8) __half xh[4], wb[4];
#pragma unroll
    for (int j = 0; j < 4; j++) {
        xh[j] = __float2half_rn(xs[j]);
        float s = (ws[j] > 0.0f) ? 1.0f : ((ws[j] < 0.0f) ? -1.0f : 0.0f);
        wb[j] = __float2half_rn(s);
    }
    size_t base = (size_t)i * 4;
    *reinterpret_cast<uint2*>(g_xh + base) = *reinterpret_cast<uint2*>(xh);
    *reinterpret_cast<uint2*>(g_wb + base) = *reinterpret_cast<uint2*>(wb);
}

// ---------------------------------------------------------------------------
// PTX helpers
// ---------------------------------------------------------------------------
__device__ __forceinline__ void cp16(uint32_t smem_addr, const void* gmem_ptr) {
    asm volatile("cp.async.cg.shared.global [%0], [%1], 16;\n"
                 :: "r"(smem_addr), "l"(gmem_ptr) : "memory");
}

__device__ __forceinline__ void ldsm_x4(uint32_t* r, uint32_t a) {
    asm volatile("ldmatrix.sync.aligned.m8n8.x4.shared.b16 {%0,%1,%2,%3}, [%4];\n"
                 : "=r"(r[0]), "=r"(r[1]), "=r"(r[2]), "=r"(r[3]) : "r"(a));
}

__device__ __forceinline__ void mma16816(float* d, const uint32_t* a,
                                         const uint32_t* b) {
    asm volatile("mma.sync.aligned.m16n8k16.row.col.f32.f16.f16.f32 "
                 "{%0,%1,%2,%3},{%4,%5,%6,%7},{%8,%9},{%0,%1,%2,%3};\n"
                 : "+f"(d[0]), "+f"(d[1]), "+f"(d[2]), "+f"(d[3])
                 : "r"(a[0]), "r"(a[1]), "r"(a[2]), "r"(a[3]),
                   "r"(b[0]), "r"(b[1]));
}

// ---------------------------------------------------------------------------
// GEMM: 128 threads = 4 warps in 2(M) x 2(N), warp tile 64x64.
// Stage layout: A rows 0-127 (128B/row XOR-swizzled); B at +16384 same.
// Swizzle: byte_off(row, ch16) = row*128 + ((ch16 ^ (row&7)) << 4)
// ---------------------------------------------------------------------------
__global__ void __launch_bounds__(128, 2)
gemm_kernel(const float* __restrict__ bias, float* __restrict__ out) {
    extern __shared__ char smem[];
    const uint32_t smem_base = (uint32_t)__cvta_generic_to_shared(smem);
    const int tid   = threadIdx.x;
    const int lane  = tid & 31;
    const int warp  = tid >> 5;
    const int warpM = warp & 1;
    const int warpN = warp >> 1;
    const int mBase = blockIdx.y * MTILE;
    const int nBase = blockIdx.x * NTILE;

    float acc[4][8][4];
#pragma unroll
    for (int a = 0; a < 4; a++)
#pragma unroll
        for (int b = 0; b < 8; b++)
#pragma unroll
            for (int c = 0; c < 4; c++) acc[a][b][c] = 0.0f;

    // ---- cp.async per-thread mapping: ch16 = tid&7, rows rbase + p*16 ----
    const int rbase = tid >> 3;               // 0..15
    const int ch    = tid & 7;
    const uint32_t swA = (uint32_t)rbase * 128 + (uint32_t)((ch ^ (rbase & 7)) << 4);
    const __half* gA = g_xh + (size_t)(mBase + rbase) * N_DIM + ch * 8;
    const __half* gB = g_wb + (size_t)(nBase + rbase) * N_DIM + ch * 8;

    auto prefetch = [&](int kt) {
        const uint32_t sb = smem_base + (uint32_t)(kt % 3) * STAGE_BYTES;
        const int k0 = kt * KTILE;
#pragma unroll
        for (int p = 0; p < 8; p++) {
            uint32_t so = swA + (uint32_t)p * 2048;      // +16 rows
            size_t go = (size_t)p * 16 * N_DIM + k0;
            cp16(sb + so,         gA + go);
            cp16(sb + 16384 + so, gB + go);
        }
        asm volatile("cp.async.commit_group;\n" ::: "memory");
    };

    // ---- ldmatrix per-thread row/offset precompute ----
    const uint32_t la7 = lane & 7;
    const uint32_t aHi = (lane >> 4) & 1;     // k +8 selector for A
    const uint32_t bHi = (lane >> 3) & 1;     // k +8 selector for B
    uint32_t aOff[4], bOff[4];
#pragma unroll
    for (int tm = 0; tm < 4; tm++) {
        uint32_t r = warpM * 64 + tm * 16 + (lane & 15);
        aOff[tm] = r * 128;
    }
#pragma unroll
    for (int pr = 0; pr < 4; pr++) {
        uint32_t r = warpN * 64 + pr * 16 + la7 + ((lane >> 4) & 1) * 8;
        bOff[pr] = 16384 + r * 128;
    }

    uint32_t ah[2][4][4], bq[2][4][4];

    auto loadfrags = [&](uint32_t sb, int ks, int buf) {
        const uint32_t ca = (((uint32_t)ks * 2 + aHi) ^ la7) << 4;
        const uint32_t cb = (((uint32_t)ks * 2 + bHi) ^ la7) << 4;
#pragma unroll
        for (int tm = 0; tm < 4; tm++) ldsm_x4(ah[buf][tm], sb + aOff[tm] + ca);
#pragma unroll
        for (int pr = 0; pr < 4; pr++) ldsm_x4(bq[buf][pr], sb + bOff[pr] + cb);
    };

    auto mmas = [&](int buf) {
#pragma unroll
        for (int tm = 0; tm < 4; tm++)
#pragma unroll
            for (int pr = 0; pr < 4; pr++) {
                mma16816(acc[tm][2 * pr],     ah[buf][tm], &bq[buf][pr][0]);
                mma16816(acc[tm][2 * pr + 1], ah[buf][tm], &bq[buf][pr][2]);
            }
    };

    prefetch(0);
    prefetch(1);
    asm volatile("cp.async.wait_group 1;\n" ::: "memory");
    __syncthreads();
    loadfrags(smem_base, 0, 0);   // (kt=0, ks=0) into buf 0

    for (int kt = 0; kt < NKT; kt++) {
        const uint32_t sb = smem_base + (uint32_t)(kt % 3) * STAGE_BYTES;
        // crunch ks0..ks2; each loads the next ks into the alternate buffer
#pragma unroll
        for (int ks = 0; ks < 3; ks++) {
            loadfrags(sb, ks + 1, (ks + 1) & 1);
            mmas(ks & 1);
        }
        // ks3 frags now sit in buf 1, NOT yet crunched.
        if (kt + 2 < NKT) prefetch(kt + 2);
        if (kt + 1 < NKT) {
            if (kt + 2 < NKT)
                asm volatile("cp.async.wait_group 1;\n" ::: "memory");
            else
                asm volatile("cp.async.wait_group 0;\n" ::: "memory");
            __syncthreads();   // stage kt+1 published; all reads of stage kt done
            // issue next ktile's ks0 LDSM, then retire ks3 under its latency
            loadfrags(smem_base + (uint32_t)((kt + 1) % 3) * STAGE_BYTES, 0, 0);
        }
        mmas(1);               // ks3 — keeps tensor pipe busy through the sync
    }

    // ---- epilogue: + bias, fp32 store ----
    const int g  = lane >> 2;
    const int t4 = lane & 3;
#pragma unroll
    for (int tm = 0; tm < 4; tm++) {
        int rr = mBase + warpM * 64 + tm * 16 + g;
#pragma unroll
        for (int tn = 0; tn < 8; tn++) {
            int col = nBase + warpN * 64 + tn * 8 + 2 * t4;
            float2 b2 = *reinterpret_cast<const float2*>(bias + col);
            float2 v0, v1;
            v0.x = acc[tm][tn][0] + b2.x;
            v0.y = acc[tm][tn][1] + b2.y;
            v1.x = acc[tm][tn][2] + b2.x;
            v1.y = acc[tm][tn][3] + b2.y;
            *reinterpret_cast<float2*>(out + (size_t)rr * N_DIM + col)       = v0;
            *reinterpret_cast<float2*>(out + (size_t)(rr + 8) * N_DIM + col) = v1;
        }
    }
}

// ---------------------------------------------------------------------------
extern "C" void kernel_launch(void* const* d_in, const int* in_sizes, int n_in,
                              void* d_out, int out_size) {
    const float* x = (const float*)d_in[0];
    const float* W = (const float*)d_in[1];
    const float* b = (const float*)d_in[2];
    float* out = (float*)d_out;

    const int n4 = (N_DIM * N_DIM) / 4;
    prep_kernel<<<(n4 + 255) / 256, 256>>>((const float4*)x, (const float4*)W, n4);

    cudaFuncSetAttribute(gemm_kernel, cudaFuncAttributeMaxDynamicSharedMemorySize,
                         SMEM_BYTES);
    dim3 grid(N_DIM / NTILE, N_DIM / MTILE);  // (32, 32)
    gemm_kernel<<<grid, 128, SMEM_BYTES>>>(b, out);
}